// round 1
// baseline (speedup 1.0000x reference)
#include <cuda_runtime.h>
#include <math.h>

// ---------------------------------------------------------------------------
// EdgeFeatureConvBlock  (B=32, N=1024, P=8192, K=16, C_IN=32, E_IN=4, OUT=64)
//
// Pipeline:
//  1. init           : top_idx = N-1, ef_t = 0, stats = 0, fb_count = 0
//  2. scatter        : sorted edge list -> per-node first-16 targets + edge feats
//  3. fb detect      : nodes whose slot0 target == N-1 -> fallback list
//  4. knn            : exact-formula KNN (top-16, stable ties) for fallback rows only
//  5. gemm<32,2>     : shortcut  sc = sc_w @ features  (+stats)
//  6. gemm<68,0>     : gather-build x (68ch) -> S0 = W0 @ x  (+stats)
//  7. finalize(0)
//  8. gemm<64,1>     : S1 = W1 @ relu(bn(S0))          (+stats)
//  9. finalize(1)
// 10. gemm<64,1>     : S2 = W2 @ relu(bn(S1))          (+stats)
// 11. finalize(2), finalize(3=sc)
// 12. final          : out = relu( bn(sc) + mean_k relu(bn(S2)) )
// ---------------------------------------------------------------------------

#define BB   32
#define NN   1024
#define PP   8192
#define KK   16
#define CIN  32
#define EIN  4
#define C0   68          // 2*CIN + EIN
#define O0   64
#define M_ALL (BB*NN*KK) // 524288
#define M_SC  (BB*NN)    // 32768
#define BN_EPS 1e-5f
#define TM   256         // GEMM column tile

// ------------------------- scratch (device globals) ------------------------
__device__ float g_S0[(size_t)O0 * M_ALL];   // 134 MB
__device__ float g_S1[(size_t)O0 * M_ALL];   // 134 MB
__device__ float g_scb[(size_t)O0 * M_SC];   // 8 MB
__device__ int   g_topidx[M_ALL];
__device__ float g_eft[BB * EIN * NN * KK];
__device__ float g_sum[4][O0];
__device__ float g_sqsum[4][O0];
__device__ float g_a[4][O0];
__device__ float g_c[4][O0];
__device__ int   g_fb_list[BB * NN];
__device__ int   g_fb_count;

// ------------------------------- init ---------------------------------------
__global__ void k_init() {
    int i = blockIdx.x * blockDim.x + threadIdx.x;
    int stride = gridDim.x * blockDim.x;
    for (int j = i; j < M_ALL; j += stride) g_topidx[j] = NN - 1;
    for (int j = i; j < BB * EIN * NN * KK; j += stride) g_eft[j] = 0.f;
    if (i < O0) {
        #pragma unroll
        for (int l = 0; l < 4; l++) { g_sum[l][i] = 0.f; g_sqsum[l][i] = 0.f; }
    }
    if (i == 0) g_fb_count = 0;
}

// ------------------------------ edge scatter --------------------------------
// src is sorted per batch; rank of edge p within its src-run via lower_bound.
__global__ void k_scatter(const int* __restrict__ edge_list,
                          const float* __restrict__ edge_feat) {
    int t = blockIdx.x * blockDim.x + threadIdx.x;
    if (t >= BB * PP) return;
    int b = t / PP, p = t % PP;
    const int* src = edge_list + (size_t)b * 2 * PP;
    const int* dst = src + PP;
    int s = src[p];
    int lo = 0, hi = p;
    while (lo < hi) { int mid = (lo + hi) >> 1; if (src[mid] < s) lo = mid + 1; else hi = mid; }
    int rank = p - lo;
    if (rank < KK) {
        g_topidx[(b * NN + s) * KK + rank] = dst[p];
        #pragma unroll
        for (int e = 0; e < EIN; e++)
            g_eft[((b * EIN + e) * NN + s) * KK + rank] =
                edge_feat[((size_t)b * EIN + e) * PP + p];
    }
}

// --------------------------- fallback detection -----------------------------
__global__ void k_fb() {
    int t = blockIdx.x * blockDim.x + threadIdx.x;
    if (t >= BB * NN) return;
    if (g_topidx[t * KK] == NN - 1) {
        int pos = atomicAdd(&g_fb_count, 1);
        g_fb_list[pos] = t;
    }
}

// ------------------------------- knn (fallback rows only) -------------------
// Matches reference formula pd = -xx_n - (-2*dot) - xx_m ; self == exactly 0
// (excluded), top-16 with stable tie-break (smaller index wins).
__global__ void k_knn(const float* __restrict__ points) {
    __shared__ float pd[NN];
    __shared__ float swv[4];
    __shared__ int   swi[4];
    int nfb = g_fb_count;
    for (int e = blockIdx.x; e < nfb; e += gridDim.x) {
        int bn = g_fb_list[e];
        int b = bn / NN, n = bn % NN;
        const float* px = points + (size_t)b * 2 * NN;
        const float* py = px + NN;
        float pxn = px[n], pyn = py[n];
        float xxn = pxn * pxn + pyn * pyn;
        for (int m = threadIdx.x; m < NN; m += blockDim.x) {
            float xm = px[m], ym = py[m];
            float inner = -2.0f * (pxn * xm + pyn * ym);
            float xxm = xm * xm + ym * ym;
            float v = -xxn - inner - xxm;
            pd[m] = (m == n) ? -INFINITY : v;
        }
        __syncthreads();
        for (int kk = 0; kk < KK; kk++) {
            float bv = -INFINITY; int bi = NN;
            for (int m = threadIdx.x; m < NN; m += blockDim.x) {
                float v = pd[m];
                if (v > bv) { bv = v; bi = m; }
            }
            #pragma unroll
            for (int off = 16; off; off >>= 1) {
                float ov = __shfl_down_sync(0xffffffffu, bv, off);
                int   oi = __shfl_down_sync(0xffffffffu, bi, off);
                if (ov > bv || (ov == bv && oi < bi)) { bv = ov; bi = oi; }
            }
            if ((threadIdx.x & 31) == 0) { swv[threadIdx.x >> 5] = bv; swi[threadIdx.x >> 5] = bi; }
            __syncthreads();
            if (threadIdx.x == 0) {
                float fv = swv[0]; int fi = swi[0];
                #pragma unroll
                for (int w = 1; w < 4; w++)
                    if (swv[w] > fv || (swv[w] == fv && swi[w] < fi)) { fv = swv[w]; fi = swi[w]; }
                g_topidx[bn * KK + kk] = fi;
                pd[fi] = -INFINITY;
            }
            __syncthreads();
        }
        __syncthreads();
    }
}

// ------------------------------- GEMM + stats -------------------------------
// C[64][M] = W[64][C] * X[C][M], block tile = 64 rows x 256 cols, 256 threads,
// 8x8 micro-tile per thread. X built in smem per MODE:
//   MODE 0: gather-build 68ch input (xi | neigh-xi | ef)
//   MODE 1: relu(a*Sin + c) from previous layer
//   MODE 2: features directly (shortcut GEMM, C=32, M=32768)
template<int C, int MODE>
__global__ __launch_bounds__(256) void k_gemm(
    const float* __restrict__ W,
    const float* __restrict__ F,      // features (mode 0/2) or Sin (mode 1)
    float* __restrict__ Sout,
    int statsIdx, int prevIdx, int Mtot)
{
    extern __shared__ __align__(16) float sm[];
    float* Ws = sm;           // [64][C] row-major (as given)
    float* Xs = sm + 64 * C;  // [C][TM]
    int tid = threadIdx.x;
    int m0 = blockIdx.x * TM;

    for (int i = tid; i < 64 * C; i += 256) Ws[i] = W[i];

    if (MODE == 0) {
        int b = m0 >> 14;                 // / (NN*KK)
        int mloc = (m0 & 16383) + tid;
        #pragma unroll
        for (int e = 0; e < EIN; e++)
            Xs[(2 * CIN + e) * TM + tid] = g_eft[(b * EIN + e) * (NN * KK) + mloc];
        int n  = mloc >> 4;
        int ng = g_topidx[m0 + tid];
        const float* Fb = F + (size_t)(b * CIN) * NN;
        #pragma unroll 8
        for (int c = 0; c < CIN; c++) {
            float xi = Fb[c * NN + n];
            float xn = Fb[c * NN + ng];
            Xs[c * TM + tid] = xi;
            Xs[(CIN + c) * TM + tid] = xn - xi;
        }
    } else if (MODE == 1) {
        const float* ga = g_a[prevIdx];
        const float* gc = g_c[prevIdx];
        for (int i = tid; i < C * (TM / 4); i += 256) {
            int c = i >> 6;               // TM/4 == 64
            int col = (i & 63) * 4;
            float4 v = *(const float4*)(F + (size_t)c * Mtot + m0 + col);
            float a = ga[c], cc = gc[c];
            float4 y;
            y.x = fmaxf(fmaf(a, v.x, cc), 0.f);
            y.y = fmaxf(fmaf(a, v.y, cc), 0.f);
            y.z = fmaxf(fmaf(a, v.z, cc), 0.f);
            y.w = fmaxf(fmaf(a, v.w, cc), 0.f);
            *(float4*)(Xs + c * TM + col) = y;
        }
    } else { // MODE 2
        int b = m0 >> 10;
        int n0 = m0 & 1023;
        for (int i = tid; i < C * (TM / 4); i += 256) {
            int c = i >> 6;
            int col = (i & 63) * 4;
            float4 v = *(const float4*)(F + (size_t)(b * CIN + c) * NN + n0 + col);
            *(float4*)(Xs + c * TM + col) = v;
        }
    }
    __syncthreads();

    int tr = tid >> 5, tc = tid & 31;
    float acc[8][8];
    #pragma unroll
    for (int r = 0; r < 8; r++)
        #pragma unroll
        for (int j = 0; j < 8; j++) acc[r][j] = 0.f;

    const float* WsBase = Ws + (size_t)(tr * 8) * C;
    #pragma unroll 4
    for (int c = 0; c < C; c++) {
        float4 x0 = *(const float4*)(Xs + c * TM + tc * 4);
        float4 x1 = *(const float4*)(Xs + c * TM + tc * 4 + 128);
        float xv[8] = {x0.x, x0.y, x0.z, x0.w, x1.x, x1.y, x1.z, x1.w};
        #pragma unroll
        for (int r = 0; r < 8; r++) {
            float w = WsBase[r * C + c];
            #pragma unroll
            for (int j = 0; j < 8; j++) acc[r][j] = fmaf(w, xv[j], acc[r][j]);
        }
    }

    // store + per-channel stats (warp rows identical -> shuffle reduce)
    #pragma unroll
    for (int r = 0; r < 8; r++) {
        int row = tr * 8 + r;
        float4 o0 = make_float4(acc[r][0], acc[r][1], acc[r][2], acc[r][3]);
        float4 o1 = make_float4(acc[r][4], acc[r][5], acc[r][6], acc[r][7]);
        *(float4*)(Sout + (size_t)row * Mtot + m0 + tc * 4) = o0;
        *(float4*)(Sout + (size_t)row * Mtot + m0 + tc * 4 + 128) = o1;
        float s = 0.f, q = 0.f;
        #pragma unroll
        for (int j = 0; j < 8; j++) { s += acc[r][j]; q += acc[r][j] * acc[r][j]; }
        #pragma unroll
        for (int off = 16; off; off >>= 1) {
            s += __shfl_down_sync(0xffffffffu, s, off);
            q += __shfl_down_sync(0xffffffffu, q, off);
        }
        if (tc == 0) {
            atomicAdd(&g_sum[statsIdx][row], s);
            atomicAdd(&g_sqsum[statsIdx][row], q);
        }
    }
}

// ------------------------------ finalize BN ---------------------------------
__global__ void k_finalize(const float* __restrict__ gamma,
                           const float* __restrict__ beta,
                           int idx, float invM) {
    int o = threadIdx.x;
    if (o < O0) {
        float m = g_sum[idx][o] * invM;
        float v = g_sqsum[idx][o] * invM - m * m;
        float a = gamma[o] / sqrtf(v + BN_EPS);
        g_a[idx][o] = a;
        g_c[idx][o] = beta[o] - m * a;
    }
}

// ------------------------------ final fuse ----------------------------------
__global__ void k_final(float* __restrict__ out) {
    int t = blockIdx.x * blockDim.x + threadIdx.x;
    if (t >= BB * O0 * NN) return;
    int n = t & (NN - 1);
    int o = (t >> 10) & 63;
    int b = t >> 16;
    float a2 = g_a[2][o], c2 = g_c[2][o];
    const float4* S = (const float4*)(g_S0 + (size_t)o * M_ALL + b * (NN * KK) + n * KK);
    float s = 0.f;
    #pragma unroll
    for (int q = 0; q < 4; q++) {
        float4 v = S[q];
        s += fmaxf(fmaf(a2, v.x, c2), 0.f) + fmaxf(fmaf(a2, v.y, c2), 0.f)
           + fmaxf(fmaf(a2, v.z, c2), 0.f) + fmaxf(fmaf(a2, v.w, c2), 0.f);
    }
    float fts = s * (1.f / KK);
    float sc = g_scb[(size_t)o * M_SC + b * NN + n];
    float v = fmaf(g_a[3][o], sc, g_c[3][o]) + fts;
    out[t] = fmaxf(v, 0.f);
}

// ------------------------------- launch -------------------------------------
extern "C" void kernel_launch(void* const* d_in, const int* in_sizes, int n_in,
                              void* d_out, int out_size) {
    const float* points    = (const float*)d_in[0];
    const float* features  = (const float*)d_in[1];
    const int*   edge_list = (const int*)d_in[2];
    const float* edge_feat = (const float*)d_in[3];
    // 'idx' scalar may or may not appear as input 4 — detect by size.
    int base = (n_in >= 17 && in_sizes[4] == 1) ? 5 : 4;
    const float* W0   = (const float*)d_in[base + 0];
    const float* W1   = (const float*)d_in[base + 1];
    const float* W2   = (const float*)d_in[base + 2];
    const float* g0   = (const float*)d_in[base + 3];
    const float* b0   = (const float*)d_in[base + 4];
    const float* g1   = (const float*)d_in[base + 5];
    const float* b1   = (const float*)d_in[base + 6];
    const float* g2   = (const float*)d_in[base + 7];
    const float* b2   = (const float*)d_in[base + 8];
    const float* sc_w = (const float*)d_in[base + 9];
    const float* sc_g = (const float*)d_in[base + 10];
    const float* sc_b = (const float*)d_in[base + 11];

    void *pS0, *pS1, *pSC;
    cudaGetSymbolAddress(&pS0, g_S0);
    cudaGetSymbolAddress(&pS1, g_S1);
    cudaGetSymbolAddress(&pSC, g_scb);
    float* S0 = (float*)pS0;
    float* S1 = (float*)pS1;
    float* SC = (float*)pSC;

    const int smem0  = (64 * C0 + C0 * TM) * 4;   // 87040
    const int smem1  = (64 * 64 + 64 * TM) * 4;   // 81920
    const int smemSC = (64 * 32 + 32 * TM) * 4;   // 40960
    cudaFuncSetAttribute(k_gemm<C0, 0>, cudaFuncAttributeMaxDynamicSharedMemorySize, smem0);
    cudaFuncSetAttribute(k_gemm<64, 1>, cudaFuncAttributeMaxDynamicSharedMemorySize, smem1);
    cudaFuncSetAttribute(k_gemm<32, 2>, cudaFuncAttributeMaxDynamicSharedMemorySize, smemSC);

    k_init<<<512, 256>>>();
    k_scatter<<<(BB * PP + 255) / 256, 256>>>(edge_list, edge_feat);
    k_fb<<<(BB * NN + 255) / 256, 256>>>();
    k_knn<<<64, 128>>>(points);

    // shortcut GEMM + stats (statsIdx 3)
    k_gemm<32, 2><<<M_SC / TM, 256, smemSC>>>(sc_w, features, SC, 3, 0, M_SC);
    // layer 0: gather + GEMM + stats
    k_gemm<C0, 0><<<M_ALL / TM, 256, smem0>>>(W0, features, S0, 0, 0, M_ALL);
    k_finalize<<<1, 64>>>(g0, b0, 0, 1.f / (float)M_ALL);
    // layer 1
    k_gemm<64, 1><<<M_ALL / TM, 256, smem1>>>(W1, S0, S1, 1, 0, M_ALL);
    k_finalize<<<1, 64>>>(g1, b1, 1, 1.f / (float)M_ALL);
    // layer 2 (writes back into S0)
    k_gemm<64, 1><<<M_ALL / TM, 256, smem1>>>(W2, S1, S0, 2, 1, M_ALL);
    k_finalize<<<1, 64>>>(g2, b2, 2, 1.f / (float)M_ALL);
    k_finalize<<<1, 64>>>(sc_g, sc_b, 3, 1.f / (float)M_SC);

    k_final<<<(BB * O0 * NN + 255) / 256, 256>>>((float*)d_out);
}

// round 2
// speedup vs baseline: 1.1777x; 1.1777x over previous
#include <cuda_runtime.h>
#include <math.h>

// ---------------------------------------------------------------------------
// EdgeFeatureConvBlock  (B=32, N=1024, P=8192, K=16, C_IN=32, E_IN=4, OUT=64)
// R2: GEMM inner loop rewritten around packed fma.rn.f32x2 (Blackwell FFMA2,
//     2x fp32 FMA lanes per issue slot, bit-identical IEEE fp32 per lane).
// ---------------------------------------------------------------------------

#define BB   32
#define NN   1024
#define PP   8192
#define KK   16
#define CIN  32
#define EIN  4
#define C0   68          // 2*CIN + EIN
#define O0   64
#define M_ALL (BB*NN*KK) // 524288
#define M_SC  (BB*NN)    // 32768
#define BN_EPS 1e-5f
#define TM   256         // GEMM column tile

typedef unsigned long long ull;

__device__ __forceinline__ ull pack2(float x, float y) {
    ull r; asm("mov.b64 %0, {%1,%2};" : "=l"(r) : "f"(x), "f"(y)); return r;
}
__device__ __forceinline__ float2 unpack2(ull v) {
    float2 r; asm("mov.b64 {%0,%1}, %2;" : "=f"(r.x), "=f"(r.y) : "l"(v)); return r;
}
#define FMA_F32X2(d, a, b, c) \
    asm("fma.rn.f32x2 %0, %1, %2, %3;" : "=l"(d) : "l"(a), "l"(b), "l"(c))

// ------------------------- scratch (device globals) ------------------------
__device__ float g_S0[(size_t)O0 * M_ALL];   // 134 MB
__device__ float g_S1[(size_t)O0 * M_ALL];   // 134 MB
__device__ float g_scb[(size_t)O0 * M_SC];   // 8 MB
__device__ int   g_topidx[M_ALL];
__device__ float g_eft[BB * EIN * NN * KK];
__device__ float g_sum[4][O0];
__device__ float g_sqsum[4][O0];
__device__ float g_a[4][O0];
__device__ float g_c[4][O0];
__device__ int   g_fb_list[BB * NN];
__device__ int   g_fb_count;

// ------------------------------- init ---------------------------------------
__global__ void k_init() {
    int i = blockIdx.x * blockDim.x + threadIdx.x;
    int stride = gridDim.x * blockDim.x;
    for (int j = i; j < M_ALL; j += stride) g_topidx[j] = NN - 1;
    for (int j = i; j < BB * EIN * NN * KK; j += stride) g_eft[j] = 0.f;
    if (i < O0) {
        #pragma unroll
        for (int l = 0; l < 4; l++) { g_sum[l][i] = 0.f; g_sqsum[l][i] = 0.f; }
    }
    if (i == 0) g_fb_count = 0;
}

// ------------------------------ edge scatter --------------------------------
__global__ void k_scatter(const int* __restrict__ edge_list,
                          const float* __restrict__ edge_feat) {
    int t = blockIdx.x * blockDim.x + threadIdx.x;
    if (t >= BB * PP) return;
    int b = t / PP, p = t % PP;
    const int* src = edge_list + (size_t)b * 2 * PP;
    const int* dst = src + PP;
    int s = src[p];
    int lo = 0, hi = p;
    while (lo < hi) { int mid = (lo + hi) >> 1; if (src[mid] < s) lo = mid + 1; else hi = mid; }
    int rank = p - lo;
    if (rank < KK) {
        g_topidx[(b * NN + s) * KK + rank] = dst[p];
        #pragma unroll
        for (int e = 0; e < EIN; e++)
            g_eft[((b * EIN + e) * NN + s) * KK + rank] =
                edge_feat[((size_t)b * EIN + e) * PP + p];
    }
}

// --------------------------- fallback detection -----------------------------
__global__ void k_fb() {
    int t = blockIdx.x * blockDim.x + threadIdx.x;
    if (t >= BB * NN) return;
    if (g_topidx[t * KK] == NN - 1) {
        int pos = atomicAdd(&g_fb_count, 1);
        g_fb_list[pos] = t;
    }
}

// ------------------------------- knn (fallback rows only) -------------------
__global__ void k_knn(const float* __restrict__ points) {
    __shared__ float pd[NN];
    __shared__ float swv[4];
    __shared__ int   swi[4];
    int nfb = g_fb_count;
    for (int e = blockIdx.x; e < nfb; e += gridDim.x) {
        int bn = g_fb_list[e];
        int b = bn / NN, n = bn % NN;
        const float* px = points + (size_t)b * 2 * NN;
        const float* py = px + NN;
        float pxn = px[n], pyn = py[n];
        float xxn = pxn * pxn + pyn * pyn;
        for (int m = threadIdx.x; m < NN; m += blockDim.x) {
            float xm = px[m], ym = py[m];
            float inner = -2.0f * (pxn * xm + pyn * ym);
            float xxm = xm * xm + ym * ym;
            float v = -xxn - inner - xxm;
            pd[m] = (m == n) ? -INFINITY : v;
        }
        __syncthreads();
        for (int kk = 0; kk < KK; kk++) {
            float bv = -INFINITY; int bi = NN;
            for (int m = threadIdx.x; m < NN; m += blockDim.x) {
                float v = pd[m];
                if (v > bv) { bv = v; bi = m; }
            }
            #pragma unroll
            for (int off = 16; off; off >>= 1) {
                float ov = __shfl_down_sync(0xffffffffu, bv, off);
                int   oi = __shfl_down_sync(0xffffffffu, bi, off);
                if (ov > bv || (ov == bv && oi < bi)) { bv = ov; bi = oi; }
            }
            if ((threadIdx.x & 31) == 0) { swv[threadIdx.x >> 5] = bv; swi[threadIdx.x >> 5] = bi; }
            __syncthreads();
            if (threadIdx.x == 0) {
                float fv = swv[0]; int fi = swi[0];
                #pragma unroll
                for (int w = 1; w < 4; w++)
                    if (swv[w] > fv || (swv[w] == fv && swi[w] < fi)) { fv = swv[w]; fi = swi[w]; }
                g_topidx[bn * KK + kk] = fi;
                pd[fi] = -INFINITY;
            }
            __syncthreads();
        }
        __syncthreads();
    }
}

// ------------------------------- GEMM + stats -------------------------------
// C[64][M] = W[64][C] * X[C][M]; block = 64 rows x 256 cols, 256 threads.
// Inner loop: packed f32x2 FMA (FFMA2). Weights pre-packed {w,w} in smem.
template<int C, int MODE>
__global__ __launch_bounds__(256, 2) void k_gemm(
    const float* __restrict__ W,
    const float* __restrict__ F,      // features (mode 0/2) or Sin (mode 1)
    float* __restrict__ Sout,
    int statsIdx, int prevIdx, int Mtot)
{
    extern __shared__ __align__(16) ull smu[];
    ull*   Wp = smu;                        // [64][C] packed {w,w}
    float* Xs = (float*)(smu + 64 * C);     // [C][TM]
    int tid = threadIdx.x;
    int m0 = blockIdx.x * TM;

    for (int i = tid; i < 64 * C; i += 256) {
        float w = W[i];
        Wp[i] = pack2(w, w);
    }

    if (MODE == 0) {
        int b = m0 >> 14;                 // / (NN*KK)
        int mloc = (m0 & 16383) + tid;
        #pragma unroll
        for (int e = 0; e < EIN; e++)
            Xs[(2 * CIN + e) * TM + tid] = g_eft[(b * EIN + e) * (NN * KK) + mloc];
        int n  = mloc >> 4;
        int ng = g_topidx[m0 + tid];
        const float* Fb = F + (size_t)(b * CIN) * NN;
        #pragma unroll 8
        for (int c = 0; c < CIN; c++) {
            float xi = Fb[c * NN + n];
            float xn = Fb[c * NN + ng];
            Xs[c * TM + tid] = xi;
            Xs[(CIN + c) * TM + tid] = xn - xi;
        }
    } else if (MODE == 1) {
        const float* ga = g_a[prevIdx];
        const float* gc = g_c[prevIdx];
        for (int i = tid; i < C * (TM / 4); i += 256) {
            int c = i >> 6;               // TM/4 == 64
            int col = (i & 63) * 4;
            float4 v = *(const float4*)(F + (size_t)c * Mtot + m0 + col);
            float a = ga[c], cc = gc[c];
            float4 y;
            y.x = fmaxf(fmaf(a, v.x, cc), 0.f);
            y.y = fmaxf(fmaf(a, v.y, cc), 0.f);
            y.z = fmaxf(fmaf(a, v.z, cc), 0.f);
            y.w = fmaxf(fmaf(a, v.w, cc), 0.f);
            *(float4*)(Xs + c * TM + col) = y;
        }
    } else { // MODE 2
        int b = m0 >> 10;
        int n0 = m0 & 1023;
        for (int i = tid; i < C * (TM / 4); i += 256) {
            int c = i >> 6;
            int col = (i & 63) * 4;
            float4 v = *(const float4*)(F + (size_t)(b * CIN + c) * NN + n0 + col);
            *(float4*)(Xs + c * TM + col) = v;
        }
    }
    __syncthreads();

    int tr = tid >> 5, tc = tid & 31;
    ull acc[8][4];
    #pragma unroll
    for (int r = 0; r < 8; r++)
        #pragma unroll
        for (int j = 0; j < 4; j++) acc[r][j] = 0ull;   // {0.f, 0.f}

    const ull* Wb = Wp + (size_t)(tr * 8) * C;
    #pragma unroll 2
    for (int c = 0; c < C; c++) {
        const float* xp = Xs + c * TM + tc * 4;
        ulonglong2 xa = *(const ulonglong2*)xp;
        ulonglong2 xb = *(const ulonglong2*)(xp + 128);
        ull xv0 = xa.x, xv1 = xa.y, xv2 = xb.x, xv3 = xb.y;
        #pragma unroll
        for (int r = 0; r < 8; r++) {
            ull w = Wb[r * C + c];
            FMA_F32X2(acc[r][0], w, xv0, acc[r][0]);
            FMA_F32X2(acc[r][1], w, xv1, acc[r][1]);
            FMA_F32X2(acc[r][2], w, xv2, acc[r][2]);
            FMA_F32X2(acc[r][3], w, xv3, acc[r][3]);
        }
    }

    // store + per-channel stats (warp rows identical -> shuffle reduce)
    #pragma unroll
    for (int r = 0; r < 8; r++) {
        int row = tr * 8 + r;
        float2 p0 = unpack2(acc[r][0]);
        float2 p1 = unpack2(acc[r][1]);
        float2 p2 = unpack2(acc[r][2]);
        float2 p3 = unpack2(acc[r][3]);
        float4 o0 = make_float4(p0.x, p0.y, p1.x, p1.y);
        float4 o1 = make_float4(p2.x, p2.y, p3.x, p3.y);
        *(float4*)(Sout + (size_t)row * Mtot + m0 + tc * 4) = o0;
        *(float4*)(Sout + (size_t)row * Mtot + m0 + tc * 4 + 128) = o1;
        float s = (p0.x + p0.y) + (p1.x + p1.y) + (p2.x + p2.y) + (p3.x + p3.y);
        float q = p0.x*p0.x + p0.y*p0.y + p1.x*p1.x + p1.y*p1.y
                + p2.x*p2.x + p2.y*p2.y + p3.x*p3.x + p3.y*p3.y;
        #pragma unroll
        for (int off = 16; off; off >>= 1) {
            s += __shfl_down_sync(0xffffffffu, s, off);
            q += __shfl_down_sync(0xffffffffu, q, off);
        }
        if (tc == 0) {
            atomicAdd(&g_sum[statsIdx][row], s);
            atomicAdd(&g_sqsum[statsIdx][row], q);
        }
    }
}

// ------------------------------ finalize BN ---------------------------------
__global__ void k_finalize(const float* __restrict__ gamma,
                           const float* __restrict__ beta,
                           int idx, float invM) {
    int o = threadIdx.x;
    if (o < O0) {
        float m = g_sum[idx][o] * invM;
        float v = g_sqsum[idx][o] * invM - m * m;
        float a = gamma[o] / sqrtf(v + BN_EPS);
        g_a[idx][o] = a;
        g_c[idx][o] = beta[o] - m * a;
    }
}

// ------------------------------ final fuse ----------------------------------
__global__ void k_final(float* __restrict__ out) {
    int t = blockIdx.x * blockDim.x + threadIdx.x;
    if (t >= BB * O0 * NN) return;
    int n = t & (NN - 1);
    int o = (t >> 10) & 63;
    int b = t >> 16;
    float a2 = g_a[2][o], c2 = g_c[2][o];
    const float4* S = (const float4*)(g_S0 + (size_t)o * M_ALL + b * (NN * KK) + n * KK);
    float s = 0.f;
    #pragma unroll
    for (int q = 0; q < 4; q++) {
        float4 v = S[q];
        s += fmaxf(fmaf(a2, v.x, c2), 0.f) + fmaxf(fmaf(a2, v.y, c2), 0.f)
           + fmaxf(fmaf(a2, v.z, c2), 0.f) + fmaxf(fmaf(a2, v.w, c2), 0.f);
    }
    float fts = s * (1.f / KK);
    float sc = g_scb[(size_t)o * M_SC + b * NN + n];
    float v = fmaf(g_a[3][o], sc, g_c[3][o]) + fts;
    out[t] = fmaxf(v, 0.f);
}

// ------------------------------- launch -------------------------------------
extern "C" void kernel_launch(void* const* d_in, const int* in_sizes, int n_in,
                              void* d_out, int out_size) {
    const float* points    = (const float*)d_in[0];
    const float* features  = (const float*)d_in[1];
    const int*   edge_list = (const int*)d_in[2];
    const float* edge_feat = (const float*)d_in[3];
    int base = (n_in >= 17 && in_sizes[4] == 1) ? 5 : 4;
    const float* W0   = (const float*)d_in[base + 0];
    const float* W1   = (const float*)d_in[base + 1];
    const float* W2   = (const float*)d_in[base + 2];
    const float* g0   = (const float*)d_in[base + 3];
    const float* b0   = (const float*)d_in[base + 4];
    const float* g1   = (const float*)d_in[base + 5];
    const float* b1   = (const float*)d_in[base + 6];
    const float* g2   = (const float*)d_in[base + 7];
    const float* b2   = (const float*)d_in[base + 8];
    const float* sc_w = (const float*)d_in[base + 9];
    const float* sc_g = (const float*)d_in[base + 10];
    const float* sc_b = (const float*)d_in[base + 11];

    void *pS0, *pS1, *pSC;
    cudaGetSymbolAddress(&pS0, g_S0);
    cudaGetSymbolAddress(&pS1, g_S1);
    cudaGetSymbolAddress(&pSC, g_scb);
    float* S0 = (float*)pS0;
    float* S1 = (float*)pS1;
    float* SC = (float*)pSC;

    const int smem0  = 64 * C0 * 8 + C0 * TM * 4;   // 104448
    const int smem1  = 64 * 64 * 8 + 64 * TM * 4;   // 98304
    const int smemSC = 64 * 32 * 8 + 32 * TM * 4;   // 49152
    cudaFuncSetAttribute(k_gemm<C0, 0>, cudaFuncAttributeMaxDynamicSharedMemorySize, smem0);
    cudaFuncSetAttribute(k_gemm<64, 1>, cudaFuncAttributeMaxDynamicSharedMemorySize, smem1);
    cudaFuncSetAttribute(k_gemm<32, 2>, cudaFuncAttributeMaxDynamicSharedMemorySize, smemSC);

    k_init<<<512, 256>>>();
    k_scatter<<<(BB * PP + 255) / 256, 256>>>(edge_list, edge_feat);
    k_fb<<<(BB * NN + 255) / 256, 256>>>();
    k_knn<<<64, 128>>>(points);

    k_gemm<32, 2><<<M_SC / TM, 256, smemSC>>>(sc_w, features, SC, 3, 0, M_SC);
    k_gemm<C0, 0><<<M_ALL / TM, 256, smem0>>>(W0, features, S0, 0, 0, M_ALL);
    k_finalize<<<1, 64>>>(g0, b0, 0, 1.f / (float)M_ALL);
    k_gemm<64, 1><<<M_ALL / TM, 256, smem1>>>(W1, S0, S1, 1, 0, M_ALL);
    k_finalize<<<1, 64>>>(g1, b1, 1, 1.f / (float)M_ALL);
    k_gemm<64, 1><<<M_ALL / TM, 256, smem1>>>(W2, S1, S0, 2, 1, M_ALL);
    k_finalize<<<1, 64>>>(g2, b2, 2, 1.f / (float)M_ALL);
    k_finalize<<<1, 64>>>(sc_g, sc_b, 3, 1.f / (float)M_SC);

    k_final<<<(BB * O0 * NN + 255) / 256, 256>>>((float*)d_out);
}

// round 5
// speedup vs baseline: 1.2486x; 1.0601x over previous
#include <cuda_runtime.h>
#include <cuda_bf16.h>
#include <math.h>
#include <stdint.h>

// ---------------------------------------------------------------------------
// EdgeFeatureConvBlock  (B=32, N=1024, P=8192, K=16, C_IN=32, E_IN=4, OUT=64)
// R5 (= R4 resubmit after infra failure): GEMMs via legacy mma.sync bf16
//     (m16n8k16) — compiles under compute_100. hi/lo bf16 3-term split for
//     fp32-class accuracy. W hoisted in registers, X in permuted smem so each
//     B fragment is one conflict-free LDS.64.
// ---------------------------------------------------------------------------

#define BB   32
#define NN   1024
#define PP   8192
#define KK   16
#define CIN  32
#define EIN  4
#define O0   64
#define M_ALL (BB*NN*KK) // 524288
#define M_SC  (BB*NN)    // 32768
#define BN_EPS 1e-5f
#define ROWB 480         // X/W smem row stride in bytes (480 % 128 == 96)

// ------------------------- scratch (device globals) ------------------------
__device__ float g_S0[(size_t)O0 * M_ALL];   // [64][M]
__device__ float g_S1[(size_t)O0 * M_ALL];
__device__ float g_scb[(size_t)O0 * M_SC];
__device__ int   g_topidx[M_ALL];
__device__ float g_eft[BB * EIN * NN * KK];
__device__ float g_sum[4][O0];
__device__ float g_sqsum[4][O0];
__device__ float g_a[4][O0];
__device__ float g_c[4][O0];
__device__ int   g_fb_list[BB * NN];
__device__ int   g_fb_count;

// ------------------------------ helpers -------------------------------------
__device__ __forceinline__ void split2(float x, __nv_bfloat16& h, __nv_bfloat16& l) {
    h = __float2bfloat16_rn(x);
    l = __float2bfloat16_rn(x - __bfloat162float(h));
}
// u16-index inside a 32B k-group for element j (0..15):
// order [0,1,8,9, 2,3,10,11, 4,5,12,13, 6,7,14,15]
__device__ __forceinline__ int pidx(int j) {
    return ((j & 6) << 1) | ((j & 8) >> 2) | (j & 1);
}
__device__ __forceinline__ void st32(char* p, const __nv_bfloat16* v) {
    *(uint4*)p        = ((const uint4*)v)[0];
    *(uint4*)(p + 16) = ((const uint4*)v)[1];
}
__device__ __forceinline__ void mma16816(float& d0, float& d1, float& d2, float& d3,
                                         uint32_t a0, uint32_t a1, uint32_t a2, uint32_t a3,
                                         uint32_t b0, uint32_t b1) {
    asm volatile(
        "mma.sync.aligned.m16n8k16.row.col.f32.bf16.bf16.f32 "
        "{%0,%1,%2,%3}, {%4,%5,%6,%7}, {%8,%9}, {%0,%1,%2,%3};"
        : "+f"(d0), "+f"(d1), "+f"(d2), "+f"(d3)
        : "r"(a0), "r"(a1), "r"(a2), "r"(a3), "r"(b0), "r"(b1));
}

// ------------------------------- init ---------------------------------------
__global__ void k_init() {
    int i = blockIdx.x * blockDim.x + threadIdx.x;
    int stride = gridDim.x * blockDim.x;
    for (int j = i; j < M_ALL; j += stride) g_topidx[j] = NN - 1;
    for (int j = i; j < BB * EIN * NN * KK; j += stride) g_eft[j] = 0.f;
    if (i < O0) {
        #pragma unroll
        for (int l = 0; l < 4; l++) { g_sum[l][i] = 0.f; g_sqsum[l][i] = 0.f; }
    }
    if (i == 0) g_fb_count = 0;
}

// ------------------------------ edge scatter --------------------------------
__global__ void k_scatter(const int* __restrict__ edge_list,
                          const float* __restrict__ edge_feat) {
    int t = blockIdx.x * blockDim.x + threadIdx.x;
    if (t >= BB * PP) return;
    int b = t / PP, p = t % PP;
    const int* src = edge_list + (size_t)b * 2 * PP;
    const int* dst = src + PP;
    int s = src[p];
    int lo = 0, hi = p;
    while (lo < hi) { int mid = (lo + hi) >> 1; if (src[mid] < s) lo = mid + 1; else hi = mid; }
    int rank = p - lo;
    if (rank < KK) {
        g_topidx[(b * NN + s) * KK + rank] = dst[p];
        #pragma unroll
        for (int e = 0; e < EIN; e++)
            g_eft[((b * EIN + e) * NN + s) * KK + rank] =
                edge_feat[((size_t)b * EIN + e) * PP + p];
    }
}

// --------------------------- fallback detection -----------------------------
__global__ void k_fb() {
    int t = blockIdx.x * blockDim.x + threadIdx.x;
    if (t >= BB * NN) return;
    if (g_topidx[t * KK] == NN - 1) {
        int pos = atomicAdd(&g_fb_count, 1);
        g_fb_list[pos] = t;
    }
}

// ------------------------------- knn (fallback rows only) -------------------
__global__ void k_knn(const float* __restrict__ points) {
    __shared__ float pd[NN];
    __shared__ float swv[4];
    __shared__ int   swi[4];
    int nfb = g_fb_count;
    for (int e = blockIdx.x; e < nfb; e += gridDim.x) {
        int bn = g_fb_list[e];
        int b = bn / NN, n = bn % NN;
        const float* px = points + (size_t)b * 2 * NN;
        const float* py = px + NN;
        float pxn = px[n], pyn = py[n];
        float xxn = pxn * pxn + pyn * pyn;
        for (int m = threadIdx.x; m < NN; m += blockDim.x) {
            float xm = px[m], ym = py[m];
            float inner = -2.0f * (pxn * xm + pyn * ym);
            float xxm = xm * xm + ym * ym;
            float v = -xxn - inner - xxm;
            pd[m] = (m == n) ? -INFINITY : v;
        }
        __syncthreads();
        for (int kk = 0; kk < KK; kk++) {
            float bv = -INFINITY; int bi = NN;
            for (int m = threadIdx.x; m < NN; m += blockDim.x) {
                float v = pd[m];
                if (v > bv) { bv = v; bi = m; }
            }
            #pragma unroll
            for (int off = 16; off; off >>= 1) {
                float ov = __shfl_down_sync(0xffffffffu, bv, off);
                int   oi = __shfl_down_sync(0xffffffffu, bi, off);
                if (ov > bv || (ov == bv && oi < bi)) { bv = ov; bi = oi; }
            }
            if ((threadIdx.x & 31) == 0) { swv[threadIdx.x >> 5] = bv; swi[threadIdx.x >> 5] = bi; }
            __syncthreads();
            if (threadIdx.x == 0) {
                float fv = swv[0]; int fi = swi[0];
                #pragma unroll
                for (int w = 1; w < 4; w++)
                    if (swv[w] > fv || (swv[w] == fv && swi[w] < fi)) { fv = swv[w]; fi = swi[w]; }
                g_topidx[bn * KK + kk] = fi;
                pd[fi] = -INFINITY;
            }
            __syncthreads();
        }
        __syncthreads();
    }
}

// --------------------------- mma GEMM + BN stats -----------------------------
// Sout[64][M] = W[64][C] * X[C][M].  K_ext = [hi(SEG)|lo(SEG)|hi(SEG)].
// CTA: 128 columns (m), 256 threads = 8 warps = 4 channel-groups x 2 m-halves.
// Warp: A = W tile (16ch x 16k) hoisted in regs; loops 8 chunks of 8 m-cols.
// MODE: 0 = gather-build 68ch, 1 = relu(bn(Sin)), 2 = features (shortcut).
template<int C, int MODE>
__global__ __launch_bounds__(256, 2) void k_gemm(
    const float* __restrict__ W,
    const float* __restrict__ F,
    float* __restrict__ Sout,
    int statsIdx, int prevIdx, int Mtot)
{
    constexpr int SEG = (C + 15) & ~15;      // 80 / 64 / 32
    constexpr int KST = (3 * SEG) / 16;      // 15 / 12 / 6
    constexpr int XOFF = 1024;
    constexpr int WOFF = XOFF + 128 * ROWB;  // 62464

    extern __shared__ __align__(16) char sm[];
    float* ca   = (float*)sm;            // [64] bn scale
    float* cb   = ca + 64;               // [64] bn shift
    float* sred = cb + 64;               // [128] block stats (sum | sqsum)
    char*  Xs   = sm + XOFF;
    char*  Ws   = sm + WOFF;

    int tid = threadIdx.x;
    int wid = tid >> 5, lane = tid & 31;
    int gm0 = blockIdx.x * 128;

    // ---- phase 1: zero / consts ----
    if (tid < 128) sred[tid] = 0.f;
    if (MODE == 1 && tid < 128)
        ((float*)sm)[tid] = (tid < 64) ? g_a[prevIdx][tid] : g_c[prevIdx][tid - 64];
    {   // zero W staging always; zero X only when padding exists (MODE 0)
        uint4 z = make_uint4(0, 0, 0, 0);
        for (int i = tid * 16; i < 64 * ROWB; i += 256 * 16) *(uint4*)(Ws + i) = z;
        if (MODE == 0)
            for (int i = tid * 16; i < 128 * ROWB; i += 256 * 16) *(uint4*)(Xs + i) = z;
    }
    __syncthreads();

    // ---- phase 2a: W_ext build (hi|hi|lo), permuted ----
    for (int i = tid; i < 64 * C; i += 256) {
        int o = i / C, c = i % C;
        float w = W[i];
        __nv_bfloat16 wh, wl; split2(w, wh, wl);
        char* row = Ws + o * ROWB;
        int g = c >> 4, pj = pidx(c & 15) * 2;
        *(__nv_bfloat16*)(row + g * 32 + pj) = wh;
        *(__nv_bfloat16*)(row + (2 * SEG / 16 + g) * 32 + pj) = wl;   // third seg: w_lo
        *(__nv_bfloat16*)(row + (SEG / 16 + g) * 32 + pj) = wh;       // second seg: w_hi
    }

    // ---- phase 2b: X build ----
    {
        int m = tid >> 1, h = tid & 1;
        int gm = gm0 + m;
        char* rowp = Xs + m * ROWB;
        if (MODE == 0) {
            int b = gm >> 14, mloc = gm & 16383;
            int n = mloc >> 4;
            int ng = g_topidx[gm];
            const float* Fb = F + (size_t)b * CIN * NN;
            #pragma unroll
            for (int blk2 = 0; blk2 < 2; blk2++) {
                __nv_bfloat16 hi[16], lo[16];
                #pragma unroll
                for (int j = 0; j < 16; j++) {
                    int c = blk2 * 16 + j;
                    float xi = Fb[c * NN + n];
                    float v = h ? (Fb[c * NN + ng] - xi) : xi;
                    int pi = pidx(j);
                    split2(v, hi[pi], lo[pi]);
                }
                // h0: k=c (grp blk2); h1: k=32+c (grp 2+blk2). lo at +SEG, dup hi at +2*SEG.
                int gbase = h * 2 + blk2;
                st32(rowp + gbase * 32, hi);
                st32(rowp + (10 + gbase) * 32, hi);
                st32(rowp + (5 + gbase) * 32, lo);
            }
            if (h == 1) {   // edge features k=64..67 (grp 4 / dup 14 / lo 9)
                __nv_bfloat16 eh[4], el[4];
                #pragma unroll
                for (int e = 0; e < 4; e++) {
                    float v = g_eft[(b * EIN + e) * (NN * KK) + mloc];
                    split2(v, eh[e], el[e]);
                }
                uint32_t h01 = (uint32_t)*(uint16_t*)&eh[0] | ((uint32_t)*(uint16_t*)&eh[1] << 16);
                uint32_t h23 = (uint32_t)*(uint16_t*)&eh[2] | ((uint32_t)*(uint16_t*)&eh[3] << 16);
                uint32_t l01 = (uint32_t)*(uint16_t*)&el[0] | ((uint32_t)*(uint16_t*)&el[1] << 16);
                uint32_t l23 = (uint32_t)*(uint16_t*)&el[2] | ((uint32_t)*(uint16_t*)&el[3] << 16);
                *(uint32_t*)(rowp + 4 * 32)      = h01;  *(uint32_t*)(rowp + 4 * 32 + 8)  = h23;
                *(uint32_t*)(rowp + 14 * 32)     = h01;  *(uint32_t*)(rowp + 14 * 32 + 8) = h23;
                *(uint32_t*)(rowp + 9 * 32)      = l01;  *(uint32_t*)(rowp + 9 * 32 + 8)  = l23;
            }
        } else if (MODE == 1) {
            #pragma unroll
            for (int blk2 = 0; blk2 < 2; blk2++) {
                __nv_bfloat16 hi[16], lo[16];
                #pragma unroll
                for (int j = 0; j < 16; j++) {
                    int c = h * 32 + blk2 * 16 + j;
                    float v = F[(size_t)c * Mtot + gm];
                    float x = fmaxf(fmaf(ca[c], v, cb[c]), 0.f);
                    int pi = pidx(j);
                    split2(x, hi[pi], lo[pi]);
                }
                int gbase = h * 2 + blk2;       // k=c
                st32(rowp + gbase * 32, hi);
                st32(rowp + (8 + gbase) * 32, hi);   // dup k=128+c
                st32(rowp + (4 + gbase) * 32, lo);   // lo  k=64+c
            }
        } else {            // MODE 2 (shortcut, C=32)
            int b = gm >> 10, n = gm & 1023;
            __nv_bfloat16 hi[16], lo[16];
            #pragma unroll
            for (int j = 0; j < 16; j++) {
                int c = h * 16 + j;
                float v = F[(size_t)(b * CIN + c) * NN + n];
                int pi = pidx(j);
                split2(v, hi[pi], lo[pi]);
            }
            st32(rowp + h * 32, hi);
            st32(rowp + (4 + h) * 32, hi);      // dup k=64+c
            st32(rowp + (2 + h) * 32, lo);      // lo  k=32+c
        }
    }
    __syncthreads();

    // ---- phase 3: hoist A fragments (weights) ----
    int cg = wid & 3, mh = wid >> 2;
    int no = cg * 16;
    int g = lane >> 2, p = lane & 3;
    uint2 A02[KST], A13[KST];
    #pragma unroll
    for (int s = 0; s < KST; s++) {
        A02[s] = *(uint2*)(Ws + (no + g) * ROWB + s * 32 + p * 8);
        A13[s] = *(uint2*)(Ws + (no + g + 8) * ROWB + s * 32 + p * 8);
    }

    // ---- phase 4: mma main loop ----
    float sA = 0.f, qA = 0.f, sB = 0.f, qB = 0.f;
    float* outA = Sout + (size_t)(no + g) * Mtot + gm0 + mh * 64 + 2 * p;
    float* outB = Sout + (size_t)(no + g + 8) * Mtot + gm0 + mh * 64 + 2 * p;
    #pragma unroll
    for (int ch = 0; ch < 8; ch++) {
        int m0 = mh * 64 + ch * 8;
        const char* brow = Xs + (m0 + g) * ROWB + p * 8;
        float d0 = 0.f, d1 = 0.f, d2 = 0.f, d3 = 0.f;
        #pragma unroll
        for (int s = 0; s < KST; s++) {
            uint2 bv = *(const uint2*)(brow + s * 32);
            mma16816(d0, d1, d2, d3, A02[s].x, A13[s].x, A02[s].y, A13[s].y, bv.x, bv.y);
        }
        *(float2*)(outA + ch * 8) = make_float2(d0, d1);
        *(float2*)(outB + ch * 8) = make_float2(d2, d3);
        sA += d0 + d1;  qA += d0 * d0 + d1 * d1;
        sB += d2 + d3;  qB += d2 * d2 + d3 * d3;
    }

    // ---- phase 5: stats reduction (quad -> smem -> global) ----
    #pragma unroll
    for (int off = 1; off <= 2; off <<= 1) {
        sA += __shfl_xor_sync(0xffffffffu, sA, off);
        qA += __shfl_xor_sync(0xffffffffu, qA, off);
        sB += __shfl_xor_sync(0xffffffffu, sB, off);
        qB += __shfl_xor_sync(0xffffffffu, qB, off);
    }
    if (p == 0) {
        atomicAdd(&sred[no + g], sA);
        atomicAdd(&sred[64 + no + g], qA);
        atomicAdd(&sred[no + g + 8], sB);
        atomicAdd(&sred[64 + no + g + 8], qB);
    }
    __syncthreads();
    if (tid < 64)        atomicAdd(&g_sum[statsIdx][tid], sred[tid]);
    else if (tid < 128)  atomicAdd(&g_sqsum[statsIdx][tid - 64], sred[tid]);
}

// ------------------------------ finalize BN ---------------------------------
__global__ void k_finalize(const float* __restrict__ gamma,
                           const float* __restrict__ beta,
                           int idx, float invM) {
    int o = threadIdx.x;
    if (o < O0) {
        float m = g_sum[idx][o] * invM;
        float v = g_sqsum[idx][o] * invM - m * m;
        float a = gamma[o] / sqrtf(v + BN_EPS);
        g_a[idx][o] = a;
        g_c[idx][o] = beta[o] - m * a;
    }
}

// ------------------------------ final fuse ----------------------------------
__global__ void k_final(float* __restrict__ out) {
    int t = blockIdx.x * blockDim.x + threadIdx.x;
    if (t >= BB * O0 * NN) return;
    int n = t & (NN - 1);
    int o = (t >> 10) & 63;
    int b = t >> 16;
    float a2 = g_a[2][o], c2 = g_c[2][o];
    const float4* S = (const float4*)(g_S0 + (size_t)o * M_ALL + b * (NN * KK) + n * KK);
    float s = 0.f;
    #pragma unroll
    for (int q = 0; q < 4; q++) {
        float4 v = S[q];
        s += fmaxf(fmaf(a2, v.x, c2), 0.f) + fmaxf(fmaf(a2, v.y, c2), 0.f)
           + fmaxf(fmaf(a2, v.z, c2), 0.f) + fmaxf(fmaf(a2, v.w, c2), 0.f);
    }
    float fts = s * (1.f / KK);
    float sc = g_scb[(size_t)o * M_SC + b * NN + n];
    float v = fmaf(g_a[3][o], sc, g_c[3][o]) + fts;
    out[t] = fmaxf(v, 0.f);
}

// ------------------------------- launch -------------------------------------
extern "C" void kernel_launch(void* const* d_in, const int* in_sizes, int n_in,
                              void* d_out, int out_size) {
    const float* points    = (const float*)d_in[0];
    const float* features  = (const float*)d_in[1];
    const int*   edge_list = (const int*)d_in[2];
    const float* edge_feat = (const float*)d_in[3];
    int base = (n_in >= 17 && in_sizes[4] == 1) ? 5 : 4;
    const float* W0   = (const float*)d_in[base + 0];
    const float* W1   = (const float*)d_in[base + 1];
    const float* W2   = (const float*)d_in[base + 2];
    const float* g0   = (const float*)d_in[base + 3];
    const float* b0   = (const float*)d_in[base + 4];
    const float* g1   = (const float*)d_in[base + 5];
    const float* b1   = (const float*)d_in[base + 6];
    const float* g2   = (const float*)d_in[base + 7];
    const float* b2   = (const float*)d_in[base + 8];
    const float* sc_w = (const float*)d_in[base + 9];
    const float* sc_g = (const float*)d_in[base + 10];
    const float* sc_b = (const float*)d_in[base + 11];

    void *pS0, *pS1, *pSC;
    cudaGetSymbolAddress(&pS0, g_S0);
    cudaGetSymbolAddress(&pS1, g_S1);
    cudaGetSymbolAddress(&pSC, g_scb);
    float* S0 = (float*)pS0;
    float* S1 = (float*)pS1;
    float* SC = (float*)pSC;

    const int smem = 1024 + 128 * ROWB + 64 * ROWB;   // 93184
    cudaFuncSetAttribute(k_gemm<68, 0>, cudaFuncAttributeMaxDynamicSharedMemorySize, smem);
    cudaFuncSetAttribute(k_gemm<64, 1>, cudaFuncAttributeMaxDynamicSharedMemorySize, smem);
    cudaFuncSetAttribute(k_gemm<32, 2>, cudaFuncAttributeMaxDynamicSharedMemorySize, smem);

    k_init<<<512, 256>>>();
    k_scatter<<<(BB * PP + 255) / 256, 256>>>(edge_list, edge_feat);
    k_fb<<<(BB * NN + 255) / 256, 256>>>();
    k_knn<<<64, 128>>>(points);

    k_gemm<32, 2><<<M_SC / 128, 256, smem>>>(sc_w, features, SC, 3, 0, M_SC);
    k_gemm<68, 0><<<M_ALL / 128, 256, smem>>>(W0, features, S0, 0, 0, M_ALL);
    k_finalize<<<1, 64>>>(g0, b0, 0, 1.f / (float)M_ALL);
    k_gemm<64, 1><<<M_ALL / 128, 256, smem>>>(W1, S0, S1, 1, 0, M_ALL);
    k_finalize<<<1, 64>>>(g1, b1, 1, 1.f / (float)M_ALL);
    k_gemm<64, 1><<<M_ALL / 128, 256, smem>>>(W2, S1, S0, 2, 1, M_ALL);
    k_finalize<<<1, 64>>>(g2, b2, 2, 1.f / (float)M_ALL);
    k_finalize<<<1, 64>>>(sc_g, sc_b, 3, 1.f / (float)M_SC);

    k_final<<<(BB * O0 * NN + 255) / 256, 256>>>((float*)d_out);
}